// round 9
// baseline (speedup 1.0000x reference)
#include <cuda_runtime.h>
#include <cstdint>

#define DIM 512
#define BATCH 32
#define M_TOTAL 131072            /* 64*64*32 */
#define MTILE 128
#define KC 32                      /* k per chunk */
#define NCHUNK (DIM/KC)            /* 16 */
#define NTHREADS 128
#define A_STRIDE 36                /* words per A smem row: banks (4g+tg)%32 bijective */
#define B_STRIDE 40                /* words per B smem row: banks (8tg+g)%32 bijective */

__device__ __forceinline__ uint32_t smem_u32(const void* p) {
    return (uint32_t)__cvta_generic_to_shared(p);
}
__device__ __forceinline__ void cp16(uint32_t dst, const void* src) {
    asm volatile("cp.async.cg.shared.global [%0], [%1], 16;" :: "r"(dst), "l"(src));
}
__device__ __forceinline__ void cp_commit() {
    asm volatile("cp.async.commit_group;" ::: "memory");
}
__device__ __forceinline__ void cp_wait1() {
    asm volatile("cp.async.wait_group 1;" ::: "memory");
}
__device__ __forceinline__ uint32_t rna_tf32(float v) {
    uint32_t bits;
    asm("cvt.rna.tf32.f32 %0, %1;" : "=r"(bits) : "f"(v));
    return bits;
}
__device__ __forceinline__ void mma_tf32(float* d, const uint32_t* a, uint32_t b0, uint32_t b1) {
    asm volatile(
        "mma.sync.aligned.m16n8k8.row.col.f32.tf32.tf32.f32 "
        "{%0,%1,%2,%3}, {%4,%5,%6,%7}, {%8,%9}, {%0,%1,%2,%3};"
        : "+f"(d[0]), "+f"(d[1]), "+f"(d[2]), "+f"(d[3])
        : "r"(a[0]), "r"(a[1]), "r"(a[2]), "r"(a[3]), "r"(b0), "r"(b1));
}

__global__ void __launch_bounds__(NTHREADS, 4)
gemm_kernel(const float* __restrict__ U, const float* __restrict__ style,
            const float* __restrict__ L, const float* __restrict__ mu,
            float* __restrict__ out)
{
    __shared__ uint32_t sA[2][MTILE * A_STRIDE];   /* 2 x 18 KB, padded rows */
    __shared__ uint32_t sB[2][KC * B_STRIDE];      /* 2 x  5 KB, padded rows */

    const int tid = threadIdx.x;
    const int wid = tid >> 5;
    const int lid = tid & 31;
    const int g   = lid >> 2;      /* groupID 0..7 */
    const int tg  = lid & 3;       /* thread-in-group 0..3 */
    const int bq  = tid & 31;      /* inline-B: this thread's b (conflict-free STS) */
    const int kq  = wid;           /* inline-B: its k-subblock of 8 (L load = warp bcast) */
    const int mbase = blockIdx.x * MTILE;

    /* A-only cp.async prefetch (exact R3 pattern) */
    auto prefetchA = [&](int c, int buf) {
        const float* ubase = U + (size_t)mbase * DIM + c * KC;
        uint32_t adst = smem_u32(&sA[buf][0]);
        #pragma unroll
        for (int j = 0; j < 8; ++j) {
            int id  = j * NTHREADS + tid;
            int row = id >> 3, seg = id & 7;
            cp16(adst + (uint32_t)(row * (A_STRIDE * 4) + seg * 16),
                 ubase + (size_t)row * DIM + seg * 4);
        }
    };

    /* inline B(c) -> sB[buf]: vectorized, transient (no regs across MMAs) */
    auto computeB = [&](int c, int buf) {
        const float4* s4 = (const float4*)(style + (size_t)bq * DIM + c * KC + kq * 8);
        const float4* l4 = (const float4*)(L + c * KC + kq * 8);
        float4 s0 = s4[0], s1 = s4[1];
        float4 l0 = l4[0], l1 = l4[1];
        uint32_t* dst = &sB[buf][(kq * 8) * B_STRIDE + bq];
        dst[0 * B_STRIDE] = rna_tf32(l0.x * s0.x);
        dst[1 * B_STRIDE] = rna_tf32(l0.y * s0.y);
        dst[2 * B_STRIDE] = rna_tf32(l0.z * s0.z);
        dst[3 * B_STRIDE] = rna_tf32(l0.w * s0.w);
        dst[4 * B_STRIDE] = rna_tf32(l1.x * s1.x);
        dst[5 * B_STRIDE] = rna_tf32(l1.y * s1.y);
        dst[6 * B_STRIDE] = rna_tf32(l1.z * s1.z);
        dst[7 * B_STRIDE] = rna_tf32(l1.w * s1.w);
    };

    float acc[2][4][4];
    #pragma unroll
    for (int mt = 0; mt < 2; ++mt)
        #pragma unroll
        for (int nt = 0; nt < 4; ++nt)
            #pragma unroll
            for (int r = 0; r < 4; ++r) acc[mt][nt][r] = 0.0f;

    prefetchA(0, 0); cp_commit();
    prefetchA(1, 1); cp_commit();
    computeB(0, 0);

    for (int c = 0; c < NCHUNK; ++c) {
        cp_wait1();
        __syncthreads();            /* A(c)+B(c) visible; all warps past c-1 reads */
        const int buf = c & 1;
        const uint32_t* A = sA[buf];
        const uint32_t* B = sB[buf];

        /* B(c+1) into sB[buf^1]: last read at c-1, safe per top barrier */
        if (c + 1 < NCHUNK) computeB(c + 1, buf ^ 1);

        #pragma unroll
        for (int ks = 0; ks < 4; ++ks) {
            uint32_t a[2][4], b[4][2];
            #pragma unroll
            for (int mt = 0; mt < 2; ++mt) {
                int rb = wid * 32 + mt * 16;
                /* +0x1000: RNE into tf32 (HW truncates low 13 bits) */
                a[mt][0] = A[(rb + g)     * A_STRIDE + ks * 8 + tg]     + 0x1000u;
                a[mt][1] = A[(rb + g + 8) * A_STRIDE + ks * 8 + tg]     + 0x1000u;
                a[mt][2] = A[(rb + g)     * A_STRIDE + ks * 8 + tg + 4] + 0x1000u;
                a[mt][3] = A[(rb + g + 8) * A_STRIDE + ks * 8 + tg + 4] + 0x1000u;
            }
            #pragma unroll
            for (int nt = 0; nt < 4; ++nt) {
                b[nt][0] = B[(ks * 8 + tg)     * B_STRIDE + nt * 8 + g];
                b[nt][1] = B[(ks * 8 + tg + 4) * B_STRIDE + nt * 8 + g];
            }
            #pragma unroll
            for (int mt = 0; mt < 2; ++mt)
                #pragma unroll
                for (int nt = 0; nt < 4; ++nt)
                    mma_tf32(acc[mt][nt], a[mt], b[nt][0], b[nt][1]);
        }

        __syncthreads();            /* all warps done reading sA[buf] */
        if (c + 2 < NCHUNK) prefetchA(c + 2, buf);
        cp_commit();                /* possibly-empty group: uniform accounting */
    }

    /* epilogue: add mu, store out[b][m] */
    #pragma unroll
    for (int mt = 0; mt < 2; ++mt) {
        int m0 = mbase + wid * 32 + mt * 16 + g;
        float mu0 = __ldg(&mu[m0]);
        float mu1 = __ldg(&mu[m0 + 8]);
        #pragma unroll
        for (int nt = 0; nt < 4; ++nt) {
            int b0 = nt * 8 + 2 * tg;
            out[(size_t)b0       * M_TOTAL + m0]     = acc[mt][nt][0] + mu0;
            out[(size_t)(b0 + 1) * M_TOTAL + m0]     = acc[mt][nt][1] + mu0;
            out[(size_t)b0       * M_TOTAL + m0 + 8] = acc[mt][nt][2] + mu1;
            out[(size_t)(b0 + 1) * M_TOTAL + m0 + 8] = acc[mt][nt][3] + mu1;
        }
    }
}

extern "C" void kernel_launch(void* const* d_in, const int* in_sizes, int n_in,
                              void* d_out, int out_size) {
    const float *style = nullptr, *U = nullptr, *L = nullptr, *mu = nullptr;
    for (int i = 0; i < n_in; ++i) {
        switch (in_sizes[i]) {
            case BATCH * DIM:   style = (const float*)d_in[i]; break;
            case M_TOTAL * DIM: U     = (const float*)d_in[i]; break;
            case DIM:           L     = (const float*)d_in[i]; break;
            case M_TOTAL:       mu    = (const float*)d_in[i]; break;
            default: break;
        }
    }
    float* out = (float*)d_out;

    gemm_kernel<<<M_TOTAL / MTILE, NTHREADS>>>(U, style, L, mu, out);
}

// round 10
// speedup vs baseline: 1.2094x; 1.2094x over previous
#include <cuda_runtime.h>
#include <cstdint>

#define DIM 512
#define BATCH 32
#define M_TOTAL 131072            /* 64*64*32 */
#define MTILE 128
#define KC 32                      /* k per chunk */
#define NCHUNK (DIM/KC)            /* 16 */
#define NTHREADS 128
#define A_STRIDE 36                /* words per A smem row: banks (4g+tg)%32 bijective */
#define B_STRIDE 40                /* words per B smem row: banks (8tg+g)%32 bijective */

__device__ __forceinline__ uint32_t smem_u32(const void* p) {
    return (uint32_t)__cvta_generic_to_shared(p);
}
__device__ __forceinline__ void cp16(uint32_t dst, const void* src) {
    asm volatile("cp.async.cg.shared.global [%0], [%1], 16;" :: "r"(dst), "l"(src));
}
__device__ __forceinline__ void cp_commit() {
    asm volatile("cp.async.commit_group;" ::: "memory");
}
__device__ __forceinline__ void cp_wait1() {
    asm volatile("cp.async.wait_group 1;" ::: "memory");
}
__device__ __forceinline__ uint32_t rna_tf32(float v) {
    uint32_t bits;
    asm("cvt.rna.tf32.f32 %0, %1;" : "=r"(bits) : "f"(v));
    return bits;
}
__device__ __forceinline__ void mma_tf32(float* d, const uint32_t* a, uint32_t b0, uint32_t b1) {
    asm volatile(
        "mma.sync.aligned.m16n8k8.row.col.f32.tf32.tf32.f32 "
        "{%0,%1,%2,%3}, {%4,%5,%6,%7}, {%8,%9}, {%0,%1,%2,%3};"
        : "+f"(d[0]), "+f"(d[1]), "+f"(d[2]), "+f"(d[3])
        : "r"(a[0]), "r"(a[1]), "r"(a[2]), "r"(a[3]), "r"(b0), "r"(b1));
}

__global__ void __launch_bounds__(NTHREADS, 4)
gemm_kernel(const float* __restrict__ U, const float* __restrict__ style,
            const float* __restrict__ L, const float* __restrict__ mu,
            float* __restrict__ out)
{
    __shared__ uint32_t sA[2][MTILE * A_STRIDE];   /* 2 x 18 KB, padded rows */
    __shared__ uint32_t sB[2][KC * B_STRIDE];      /* 2 x  5 KB, padded rows */

    const int tid = threadIdx.x;
    const int wid = tid >> 5;
    const int lid = tid & 31;
    const int g   = lid >> 2;      /* groupID 0..7 */
    const int tg  = lid & 3;       /* thread-in-group 0..3 */
    const int fo  = tid & 7;       /* inline-B: float4 offset in k (coalesced) */
    const int b0  = tid >> 3;      /* inline-B: b rows b0 and b0+16 */
    const int mbase = blockIdx.x * MTILE;

    /* A-only cp.async prefetch (exact R3 pattern) */
    auto prefetchA = [&](int c, int buf) {
        const float* ubase = U + (size_t)mbase * DIM + c * KC;
        uint32_t adst = smem_u32(&sA[buf][0]);
        #pragma unroll
        for (int j = 0; j < 8; ++j) {
            int id  = j * NTHREADS + tid;
            int row = id >> 3, seg = id & 7;
            cp16(adst + (uint32_t)(row * (A_STRIDE * 4) + seg * 16),
                 ubase + (size_t)row * DIM + seg * 4);
        }
    };

    /* inline-B phase 1: coalesced loads (8 lanes = 128B contiguous per style row) */
    auto loadB = [&](int c, float4& s0, float4& s1, float4& lv) {
        const float4* s4 = (const float4*)style;
        const float4* l4 = (const float4*)L;
        s0 = s4[(size_t)b0        * (DIM / 4) + c * 8 + fo];
        s1 = s4[(size_t)(b0 + 16) * (DIM / 4) + c * 8 + fo];
        lv = l4[c * 8 + fo];
    };
    /* inline-B phase 2: mul + rna + STS (rotated order -> <=2-way bank conflicts) */
    auto storeB = [&](int buf, const float4& s0, const float4& s1, const float4& lv) {
        float p0[4] = {lv.x * s0.x, lv.y * s0.y, lv.z * s0.z, lv.w * s0.w};
        float p1[4] = {lv.x * s1.x, lv.y * s1.y, lv.z * s1.z, lv.w * s1.w};
        int koff = fo * 4;
        #pragma unroll
        for (int jj = 0; jj < 4; ++jj) {
            int j = (jj + fo) & 3;
            sB[buf][(koff + j) * B_STRIDE + b0]      = rna_tf32(p0[j]);
            sB[buf][(koff + j) * B_STRIDE + b0 + 16] = rna_tf32(p1[j]);
        }
    };

    float acc[2][4][4];
    #pragma unroll
    for (int mt = 0; mt < 2; ++mt)
        #pragma unroll
        for (int nt = 0; nt < 4; ++nt)
            #pragma unroll
            for (int r = 0; r < 4; ++r) acc[mt][nt][r] = 0.0f;

    prefetchA(0, 0); cp_commit();
    prefetchA(1, 1); cp_commit();
    {   /* B(0) one-time */
        float4 s0, s1, lv;
        loadB(0, s0, s1, lv);
        storeB(0, s0, s1, lv);
    }

    for (int c = 0; c < NCHUNK; ++c) {
        cp_wait1();
        __syncthreads();            /* A(c)+B(c) visible; all warps past c-1 reads */
        const int buf = c & 1;
        const uint32_t* A = sA[buf];
        const uint32_t* B = sB[buf];

        /* issue B(c+1) loads now; latency hides under the MMA block */
        float4 s0, s1, lv;
        const bool doB = (c + 1 < NCHUNK);
        if (doB) loadB(c + 1, s0, s1, lv);

        #pragma unroll
        for (int ks = 0; ks < 4; ++ks) {
            uint32_t a[2][4], b[4][2];
            #pragma unroll
            for (int mt = 0; mt < 2; ++mt) {
                int rb = wid * 32 + mt * 16;
                /* +0x1000: RNE into tf32 (HW truncates low 13 bits) */
                a[mt][0] = A[(rb + g)     * A_STRIDE + ks * 8 + tg]     + 0x1000u;
                a[mt][1] = A[(rb + g + 8) * A_STRIDE + ks * 8 + tg]     + 0x1000u;
                a[mt][2] = A[(rb + g)     * A_STRIDE + ks * 8 + tg + 4] + 0x1000u;
                a[mt][3] = A[(rb + g + 8) * A_STRIDE + ks * 8 + tg + 4] + 0x1000u;
            }
            #pragma unroll
            for (int nt = 0; nt < 4; ++nt) {
                b[nt][0] = B[(ks * 8 + tg)     * B_STRIDE + nt * 8 + g];
                b[nt][1] = B[(ks * 8 + tg + 4) * B_STRIDE + nt * 8 + g];
            }
            #pragma unroll
            for (int mt = 0; mt < 2; ++mt)
                #pragma unroll
                for (int nt = 0; nt < 4; ++nt)
                    mma_tf32(acc[mt][nt], a[mt], b[nt][0], b[nt][1]);
        }

        /* B(c+1) stores into sB[buf^1]: last read at c-1, safe per top barrier */
        if (doB) storeB(buf ^ 1, s0, s1, lv);

        __syncthreads();            /* all warps done reading sA[buf] */
        if (c + 2 < NCHUNK) prefetchA(c + 2, buf);
        cp_commit();                /* possibly-empty group: uniform accounting */
    }

    /* epilogue: add mu, store out[b][m] */
    #pragma unroll
    for (int mt = 0; mt < 2; ++mt) {
        int m0 = mbase + wid * 32 + mt * 16 + g;
        float mu0 = __ldg(&mu[m0]);
        float mu1 = __ldg(&mu[m0 + 8]);
        #pragma unroll
        for (int nt = 0; nt < 4; ++nt) {
            int bb = nt * 8 + 2 * tg;
            out[(size_t)bb       * M_TOTAL + m0]     = acc[mt][nt][0] + mu0;
            out[(size_t)(bb + 1) * M_TOTAL + m0]     = acc[mt][nt][1] + mu0;
            out[(size_t)bb       * M_TOTAL + m0 + 8] = acc[mt][nt][2] + mu1;
            out[(size_t)(bb + 1) * M_TOTAL + m0 + 8] = acc[mt][nt][3] + mu1;
        }
    }
}

extern "C" void kernel_launch(void* const* d_in, const int* in_sizes, int n_in,
                              void* d_out, int out_size) {
    const float *style = nullptr, *U = nullptr, *L = nullptr, *mu = nullptr;
    for (int i = 0; i < n_in; ++i) {
        switch (in_sizes[i]) {
            case BATCH * DIM:   style = (const float*)d_in[i]; break;
            case M_TOTAL * DIM: U     = (const float*)d_in[i]; break;
            case DIM:           L     = (const float*)d_in[i]; break;
            case M_TOTAL:       mu    = (const float*)d_in[i]; break;
            default: break;
        }
    }
    float* out = (float*)d_out;

    gemm_kernel<<<M_TOTAL / MTILE, NTHREADS>>>(U, style, L, mu, out);
}